// round 5
// baseline (speedup 1.0000x reference)
#include <cuda_runtime.h>
#include <math.h>

#define Bx   4
#define Tx   12
#define Nx   3000
#define Hx   64
#define Mx   32
#define Ex   96000
#define GMMx 96
#define RINx 161
#define GINx 225
#define D3x  675
#define BNx  (Bx*Nx)
#define Rr   16
#define NBLK (BNx/Rr)     // 750

#define KIN  164          // padded [h(64), x(1), xs1(96), pad(3)]
#define KRU  680          // padded 675
#define KP4_G   16
#define KP4_IN  41
#define KP4_SD  32
#define KP4_OUT 32
#define KP4_RU  170
#define KP4_C   170

// ---------------- device scratch ----------------
__device__ int   g_cnt[Nx];
__device__ int   g_cur[Nx];
__device__ int   g_off[Nx + 1];
__device__ int   g_eid[Ex];
__device__ int   g_srcs[Ex];
__device__ float g_ws[Ex];

__device__ float g_h   [BNx * Hx];
__device__ float g_z   [BNx * Hx];
__device__ float g_az  [BNx * Hx];
__device__ float g_Ah  [BNx * Hx];
__device__ float g_AAh [BNx * Hx];
__device__ float g_repr[BNx * 2 * Hx];
__device__ float g_x2  [BNx * RINx];
__device__ float g_Ax2 [BNx * RINx];
__device__ float g_AAx2[BNx * RINx];
__device__ float g_rh  [BNx * Hx];
__device__ float g_Arh [BNx * Hx];
__device__ float g_AArh[BNx * Hx];
__device__ float g_gg  [BNx * Hx];

// interleaved-transposed weights: [K/4][NC][4]
__device__ __align__(16) float w4_g  [KP4_G   * GMMx * 4];
__device__ __align__(16) float w4_in [KP4_IN  * Hx   * 4];
__device__ __align__(16) float w4_sd [KP4_SD  * Hx   * 4];
__device__ __align__(16) float w4_out[KP4_OUT * RINx * 4];
__device__ __align__(16) float w4_ru [KP4_RU  * 2*Hx * 4];
__device__ __align__(16) float w4_c  [KP4_C   * Hx   * 4];

// ---------------- preprocessing: CSR by dst, deterministic ----------------
__global__ void k_init() {
    int i = blockIdx.x * blockDim.x + threadIdx.x;
    if (i < Nx) { g_cnt[i] = 0; g_cur[i] = 0; }
    if (i < BNx * Hx) g_h[i] = 0.f;
}
__global__ void k_count(const int* __restrict__ ei) {
    int e = blockIdx.x * blockDim.x + threadIdx.x;
    if (e < Ex) atomicAdd(&g_cnt[ei[Ex + e]], 1);
}
__global__ void k_scan() {
    int lane = threadIdx.x;
    const int CH = (Nx + 31) / 32;
    int st = lane * CH, en = min(Nx, st + CH);
    int s = 0;
    for (int i = st; i < en; i++) s += g_cnt[i];
    int acc = s;
    for (int o = 1; o < 32; o <<= 1) {
        int v = __shfl_up_sync(0xffffffffu, acc, o);
        if (lane >= o) acc += v;
    }
    int base = acc - s;
    for (int i = st; i < en; i++) { g_off[i] = base; base += g_cnt[i]; }
    if (lane == 31) g_off[Nx] = base;
}
__global__ void k_scatter(const int* __restrict__ ei) {
    int e = blockIdx.x * blockDim.x + threadIdx.x;
    if (e < Ex) {
        int d = ei[Ex + e];
        int p = atomicAdd(&g_cur[d], 1);
        g_eid[g_off[d] + p] = e;
    }
}
__global__ void k_sortfill(const int* __restrict__ ei, const float* __restrict__ ew) {
    int d = blockIdx.x * blockDim.x + threadIdx.x;
    if (d >= Nx) return;
    int s = g_off[d], t = g_off[d + 1];
    for (int i = s + 1; i < t; i++) {
        int v = g_eid[i];
        int j = i - 1;
        while (j >= s && g_eid[j] > v) { g_eid[j + 1] = g_eid[j]; j--; }
        g_eid[j + 1] = v;
    }
    for (int i = s; i < t; i++) {
        int e = g_eid[i];
        g_srcs[i] = ei[e];
        g_ws[i]   = ew[e];
    }
}

// weight transform: W[K][NC] -> W4[K/4][NCdst][4]; mode 1 permutes K to [h,x,xs1]
__global__ void k_mkw4(int mode, const float* __restrict__ W) {
    int idx = blockIdx.x * blockDim.x + threadIdx.x;
    int Kreal, NCsrc, NCdst, KP4, coff; float* dst;
    switch (mode) {
        case 0:  Kreal = 64;  NCsrc = GMMx; NCdst = GMMx; KP4 = KP4_G;   coff = 0;  dst = w4_g;   break;
        case 1:  Kreal = 164; NCsrc = Hx;   NCdst = Hx;   KP4 = KP4_IN;  coff = 0;  dst = w4_in;  break;
        case 2:  Kreal = 128; NCsrc = Hx;   NCdst = Hx;   KP4 = KP4_SD;  coff = 0;  dst = w4_sd;  break;
        case 3:  Kreal = 128; NCsrc = RINx; NCdst = RINx; KP4 = KP4_OUT; coff = 0;  dst = w4_out; break;
        case 4:  Kreal = D3x; NCsrc = Hx;   NCdst = 2*Hx; KP4 = KP4_RU;  coff = 0;  dst = w4_ru;  break;
        case 5:  Kreal = D3x; NCsrc = Hx;   NCdst = 2*Hx; KP4 = KP4_RU;  coff = Hx; dst = w4_ru;  break;
        default: Kreal = D3x; NCsrc = Hx;   NCdst = Hx;   KP4 = KP4_C;   coff = 0;  dst = w4_c;   break;
    }
    int total = KP4 * NCsrc * 4;
    if (idx >= total) return;
    int i = idx & 3;
    int rest = idx >> 2;
    int c = rest % NCsrc;
    int kk = rest / NCsrc;
    int k = kk * 4 + i;
    float v = 0.f;
    if (mode == 1) {
        int src = (k < 64) ? (97 + k) : (k == 64 ? 0 : (k < 161 ? k - 64 : -1));
        if (src >= 0) v = W[(size_t)src * NCsrc + c];
    } else if (k < Kreal) {
        v = W[(size_t)k * NCsrc + c];
    }
    dst[(size_t)kk * NCdst * 4 + (size_t)(c + coff) * 4 + i] = v;
}

// 16-row GEMM core: col, sh, acc[16] defined in kernel
#define GEMM16(KP4, NC, W4ARR, STRIDE)                                   \
    {                                                                    \
        const float4* W4p = (const float4*)(W4ARR);                      \
        for (int kk = 0; kk < (KP4); kk++) {                             \
            float4 w = __ldg(&W4p[kk * (NC) + col]);                     \
            _Pragma("unroll")                                            \
            for (int r = 0; r < Rr; r++) {                               \
                float4 v = *(const float4*)(sh + r * (STRIDE) + kk * 4); \
                acc[r] = fmaf(w.x, v.x, acc[r]);                         \
                acc[r] = fmaf(w.y, v.y, acc[r]);                         \
                acc[r] = fmaf(w.z, v.z, acc[r]);                         \
                acc[r] = fmaf(w.w, v.w, acc[r]);                         \
            }                                                            \
        }                                                                \
    }

// ---------------- step kernels ----------------
// fused: raw = h@W_gmm+b -> activations -> xs1 (smem) ; z = [x,xs1,h]@W_in+b
__global__ void k_gz(const float* __restrict__ x, const float* __restrict__ bg,
                     const float* __restrict__ bi, float* __restrict__ pred_out, int t) {
    __shared__ __align__(16) float sh[Rr * KIN];   // [r][ h(64) x(1) xs1(96) pad(3) ]
    int tid = threadIdx.x;               // 0..95
    int row0 = blockIdx.x * Rr;
    #pragma unroll
    for (int r = 0; r < Rr; r++)
        for (int k = tid; k < Hx; k += 96)
            sh[r * KIN + k] = g_h[(size_t)(row0 + r) * Hx + k];
    if (tid < Rr) {
        int row = row0 + tid;
        int b = row / Nx, n = row - b * Nx;
        sh[tid * KIN + 64] = x[((size_t)b * Tx + t) * Nx + n];
        sh[tid * KIN + 161] = 0.f;
        sh[tid * KIN + 162] = 0.f;
        sh[tid * KIN + 163] = 0.f;
    }
    __syncthreads();
    // phase 1: gmm (96 cols)
    {
        float acc[Rr];
        float b0 = bg[tid];
        #pragma unroll
        for (int r = 0; r < Rr; r++) acc[r] = b0;
        int col = tid;
        GEMM16(KP4_G, GMMx, w4_g, KIN);
        #pragma unroll
        for (int r = 0; r < Rr; r++) {
            float a = acc[r], val;
            if (tid < Mx) {
                val = a;
            } else if (tid < 2 * Mx) {
                val = fmaxf(a, 0.f) + log1pf(expf(-fabsf(a)));
            } else {
                float m = a;
                for (int o = 16; o; o >>= 1) m = fmaxf(m, __shfl_xor_sync(0xffffffffu, m, o));
                float ex = expf(a - m);
                float s = ex;
                for (int o = 16; o; o >>= 1) s += __shfl_xor_sync(0xffffffffu, s, o);
                val = ex / s;
            }
            sh[r * KIN + 65 + tid] = val;
            int row = row0 + r;
            int b = row / Nx, n = row - b * Nx;
            pred_out[(((size_t)b * Tx + t) * Nx + n) * GMMx + tid] = val;
        }
    }
    __syncthreads();
    // phase 2: zin (64 cols)
    if (tid < Hx) {
        float acc[Rr];
        float b0 = bi[tid];
        #pragma unroll
        for (int r = 0; r < Rr; r++) acc[r] = b0;
        int col = tid;
        GEMM16(KP4_IN, Hx, w4_in, KIN);
        #pragma unroll
        for (int r = 0; r < Rr; r++)
            g_z[(size_t)(row0 + r) * Hx + tid] = acc[r];
    }
}

// gather aggregation, device-side pointer resolution
// mode 0: az=A z(64), Ah=A h(64)  128 thr
// mode 1: Ax2=A x2(161)           192 thr
// mode 2: AAx2=A Ax2(161), AAh=A Ah(64)  256 thr
// mode 3: Arh=A rh(64)            64 thr
// mode 4: AArh=A Arh(64)          64 thr
__global__ void k_agg(int mode) {
    const float* A; const float* Bp = 0; float* OA; float* OB = 0;
    int dA, dB = 0;
    switch (mode) {
        case 0:  A = g_z;   dA = Hx;   OA = g_az;   Bp = g_h;  dB = Hx; OB = g_Ah;  break;
        case 1:  A = g_x2;  dA = RINx; OA = g_Ax2;                                  break;
        case 2:  A = g_Ax2; dA = RINx; OA = g_AAx2; Bp = g_Ah; dB = Hx; OB = g_AAh; break;
        case 3:  A = g_rh;  dA = Hx;   OA = g_Arh;                                  break;
        default: A = g_Arh; dA = Hx;   OA = g_AArh;                                 break;
    }
    int blk = blockIdx.x;
    int b = blk / Nx, d = blk - b * Nx;
    int tid = threadIdx.x;
    int s0 = g_off[d], s1 = g_off[d + 1];
    __shared__ int   ss[64];
    __shared__ float sw[64];
    bool inA = tid < dA;
    bool active = tid < dA + dB;
    int dim = inA ? dA : dB;
    int c   = inA ? tid : tid - dA;
    const float* P = inA ? (A + (size_t)b * Nx * dA) : (Bp + (size_t)b * Nx * dB);
    float acc = 0.f;
    for (int base = s0; base < s1; base += 64) {
        int m = min(64, s1 - base);
        __syncthreads();
        if (tid < m) { ss[tid] = g_srcs[base + tid]; sw[tid] = g_ws[base + tid]; }
        __syncthreads();
        if (active) {
            for (int i = 0; i < m; i++)
                acc = fmaf(sw[i], P[(size_t)ss[i] * dim + c], acc);
        }
    }
    if (active) {
        if (inA) OA[(size_t)blk * dA + c] = acc;
        else     OB[(size_t)blk * dB + c] = acc;
    }
}

// conv = [z,az]@W_sd+b; repr = relu([conv,h])
__global__ void k_sd(const float* __restrict__ bsd, float* __restrict__ reps_out, int t) {
    __shared__ __align__(16) float sh[Rr * 2 * Hx];
    int tid = threadIdx.x;               // 0..63
    int row0 = blockIdx.x * Rr;
    #pragma unroll
    for (int r = 0; r < Rr; r++) {
        int row = row0 + r;
        sh[r * 128 + tid]      = g_z [(size_t)row * Hx + tid];
        sh[r * 128 + Hx + tid] = g_az[(size_t)row * Hx + tid];
    }
    __syncthreads();
    float acc[Rr];
    float b0 = bsd[tid];
    #pragma unroll
    for (int r = 0; r < Rr; r++) acc[r] = b0;
    int col = tid;
    GEMM16(KP4_SD, Hx, w4_sd, 128);
    #pragma unroll
    for (int r = 0; r < Rr; r++) {
        int row = row0 + r;
        float v1 = fmaxf(acc[r], 0.f);
        float v2 = fmaxf(g_h[(size_t)row * Hx + tid], 0.f);
        g_repr[(size_t)row * 2 * Hx + tid]      = v1;
        g_repr[(size_t)row * 2 * Hx + Hx + tid] = v2;
        int b = row / Nx, n = row - b * Nx;
        size_t o = (((size_t)b * Tx + t) * Nx + n) * (2 * Hx);
        reps_out[o + tid]      = v1;
        reps_out[o + Hx + tid] = v2;
    }
}

// x2 = repr @ W_out + b_out
__global__ void k_out(const float* __restrict__ bout, float* __restrict__ gen_out, int t) {
    __shared__ __align__(16) float sh[Rr * 2 * Hx];
    int tid = threadIdx.x;               // 0..191
    int row0 = blockIdx.x * Rr;
    for (int idx = tid; idx < Rr * 2 * Hx; idx += 192)
        sh[idx] = g_repr[(size_t)row0 * 2 * Hx + idx];   // tile rows contiguous
    __syncthreads();
    if (tid >= RINx) return;
    float acc[Rr];
    float b0 = bout[tid];
    #pragma unroll
    for (int r = 0; r < Rr; r++) acc[r] = b0;
    int col = tid;
    GEMM16(KP4_OUT, RINx, w4_out, 128);
    #pragma unroll
    for (int r = 0; r < Rr; r++) {
        int row = row0 + r;
        g_x2[(size_t)row * RINx + tid] = acc[r];
        int b = row / Nx, n = row - b * Nx;
        gen_out[(((size_t)b * Tx + t) * Nx + n) * RINx + tid] = acc[r];
    }
}

// load 675-dim concat row-major: [x2, P, Ax2, AP, AAx2, AAP] + zero pad
__device__ __forceinline__ void load675(float* __restrict__ sh, int row0, int tid, int nthr,
                                        const float* __restrict__ P,
                                        const float* __restrict__ AP,
                                        const float* __restrict__ AAP) {
    #pragma unroll
    for (int r = 0; r < Rr; r++) {
        int row = row0 + r;
        float* dst = sh + r * KRU;
        for (int k = tid; k < RINx; k += nthr) dst[k]       = g_x2  [(size_t)row * RINx + k];
        for (int k = tid; k < Hx;   k += nthr) dst[161 + k] = P     [(size_t)row * Hx   + k];
        for (int k = tid; k < RINx; k += nthr) dst[225 + k] = g_Ax2 [(size_t)row * RINx + k];
        for (int k = tid; k < Hx;   k += nthr) dst[386 + k] = AP    [(size_t)row * Hx   + k];
        for (int k = tid; k < RINx; k += nthr) dst[450 + k] = g_AAx2[(size_t)row * RINx + k];
        for (int k = tid; k < Hx;   k += nthr) dst[611 + k] = AAP   [(size_t)row * Hx   + k];
        if (tid < 5) dst[675 + tid] = 0.f;
    }
}

// r,u gates: 128 threads; cols 0..63 -> W_r, 64..127 -> W_u; rh = r*h, gg = g
__global__ void k_ru(const float* __restrict__ br, const float* __restrict__ bu) {
    __shared__ __align__(16) float sh[Rr * KRU];
    int tid = threadIdx.x;
    int row0 = blockIdx.x * Rr;
    load675(sh, row0, tid, 128, g_h, g_Ah, g_AAh);
    __syncthreads();
    int c64 = tid & 63;
    float acc[Rr];
    float b0 = (tid < Hx) ? br[c64] : bu[c64];
    #pragma unroll
    for (int r = 0; r < Rr; r++) acc[r] = b0;
    int col = tid;
    GEMM16(KP4_RU, 2 * Hx, w4_ru, KRU);
    #pragma unroll
    for (int r = 0; r < Rr; r++) {
        int row = row0 + r;
        float sg = 1.f / (1.f + expf(-acc[r]));
        if (tid < Hx) g_rh[(size_t)row * Hx + c64] = sg * sh[r * KRU + 161 + c64]; // r*h
        else          g_gg[(size_t)row * Hx + c64] = sg;
    }
}

// c = tanh(...); h = g*h + (1-g)*c
__global__ void k_c(const float* __restrict__ bc, float* __restrict__ st_out, int t) {
    __shared__ __align__(16) float sh[Rr * KRU];
    int tid = threadIdx.x;               // 0..63
    int row0 = blockIdx.x * Rr;
    load675(sh, row0, tid, 64, g_rh, g_Arh, g_AArh);
    __syncthreads();
    float acc[Rr];
    float b0 = bc[tid];
    #pragma unroll
    for (int r = 0; r < Rr; r++) acc[r] = b0;
    int col = tid;
    GEMM16(KP4_C, Hx, w4_c, KRU);
    #pragma unroll
    for (int r = 0; r < Rr; r++) {
        int row = row0 + r;
        float c = tanhf(acc[r]);
        float gg = g_gg[(size_t)row * Hx + tid];
        float h  = g_h [(size_t)row * Hx + tid];
        float hn = gg * h + (1.f - gg) * c;
        g_h[(size_t)row * Hx + tid] = hn;
        int b = row / Nx, n = row - b * Nx;
        st_out[(((size_t)b * Tx + t) * Nx + n) * Hx + tid] = hn;
    }
}

// ---------------- launch ----------------
extern "C" void kernel_launch(void* const* d_in, const int* in_sizes, int n_in,
                              void* d_out, int out_size) {
    const float* x    = (const float*)d_in[0];
    const int*   ei   = (const int*)  d_in[1];
    const float* ew   = (const float*)d_in[2];
    const float* Wg   = (const float*)d_in[3];
    const float* bg   = (const float*)d_in[4];
    const float* Wi   = (const float*)d_in[5];
    const float* bi   = (const float*)d_in[6];
    const float* Wsd  = (const float*)d_in[7];
    const float* bsd  = (const float*)d_in[8];
    const float* Wout = (const float*)d_in[9];
    const float* bout = (const float*)d_in[10];
    const float* Wr   = (const float*)d_in[11];
    const float* br   = (const float*)d_in[12];
    const float* Wu   = (const float*)d_in[13];
    const float* bu   = (const float*)d_in[14];
    const float* Wc   = (const float*)d_in[15];
    const float* bc   = (const float*)d_in[16];

    float* out  = (float*)d_out;
    float* gen  = out;
    float* pred = out + (size_t)Bx * Tx * Nx * RINx;
    float* reps = pred + (size_t)Bx * Tx * Nx * GMMx;
    float* st   = reps + (size_t)Bx * Tx * Nx * (2 * Hx);

    k_init    <<<(BNx * Hx + 255) / 256, 256>>>();
    k_count   <<<(Ex + 255) / 256, 256>>>(ei);
    k_scan    <<<1, 32>>>();
    k_scatter <<<(Ex + 255) / 256, 256>>>(ei);
    k_sortfill<<<(Nx + 127) / 128, 128>>>(ei, ew);

    // weight transforms
    {
        const int tot[7] = { KP4_G*GMMx*4, KP4_IN*Hx*4, KP4_SD*Hx*4, KP4_OUT*RINx*4,
                             KP4_RU*Hx*4, KP4_RU*Hx*4, KP4_C*Hx*4 };
        const float* Ws[7] = { Wg, Wi, Wsd, Wout, Wr, Wu, Wc };
        for (int m = 0; m < 7; m++)
            k_mkw4<<<(tot[m] + 255) / 256, 256>>>(m, Ws[m]);
    }

    for (int t = 0; t < Tx; t++) {
        k_gz <<<NBLK, 96>>>(x, bg, bi, pred, t);
        k_agg<<<BNx, 128>>>(0);                 // az, Ah
        k_sd <<<NBLK, 64>>>(bsd, reps, t);
        k_out<<<NBLK, 192>>>(bout, gen, t);
        k_agg<<<BNx, 192>>>(1);                 // Ax2
        k_agg<<<BNx, 256>>>(2);                 // AAx2, AAh
        k_ru <<<NBLK, 128>>>(br, bu);
        k_agg<<<BNx, 64>>>(3);                  // Arh
        k_agg<<<BNx, 64>>>(4);                  // AArh
        k_c  <<<NBLK, 64>>>(bc, st, t);
    }
}